// round 12
// baseline (speedup 1.0000x reference)
#include <cuda_runtime.h>
#include <cuda_bf16.h>
#include <cuda_fp16.h>
#include <cstdint>

typedef unsigned long long ull;

constexpr int T_ = 64, B_ = 64, N_ = 64, D_ = 128, HID_ = 256;
constexpr int BND = B_ * N_ * D_;                      // 524288
constexpr size_t TOT  = (size_t)T_ * BND;              // 33554432
constexpr size_t TOTH = (size_t)T_ * B_ * N_ * HID_;   // 67108864

// -------- scratch (no allocations allowed) --------
__device__ float g_M[64 * 64];
__device__ ull   g_Mp[32 * 64];
__device__ __half g_xs[2][TOT];
__device__ __half g_ms[2][TOT];
__device__ __half g_os[2][TOT];
__device__ __half g_xgs[2][TOT];
__device__ float  g_xg[TOT];
__device__ __half g_q[TOT];
__device__ __half g_k[TOT];
__device__ __half g_v[TOT];
__device__ __half g_h1[TOTH];
__device__ __half g_wsp[7][2 * 128 * 256];

// -------- helpers --------
__device__ __forceinline__ void ffma2(ull& d, ull a, ull b) {
    asm("fma.rn.f32x2 %0, %1, %2, %0;" : "+l"(d) : "l"(a), "l"(b));
}
__device__ __forceinline__ ull dup2(float x) {
    ull r; unsigned u = __float_as_uint(x);
    asm("mov.b64 %0, {%1, %1};" : "=l"(r) : "r"(u));
    return r;
}
__device__ __forceinline__ ull pack2(float lo, float hi) {
    ull r;
    asm("mov.b64 %0, {%1, %2};" : "=l"(r) : "r"(__float_as_uint(lo)), "r"(__float_as_uint(hi)));
    return r;
}
__device__ __forceinline__ uint32_t smem_u32(const void* p) {
    uint32_t a;
    asm("{ .reg .u64 t; cvta.to.shared.u64 t, %1; cvt.u32.u64 %0, t; }" : "=r"(a) : "l"(p));
    return a;
}
__device__ __forceinline__ uint32_t sw128(uint32_t off) { return off ^ ((off >> 3) & 0x70); }
__device__ __forceinline__ void ldsm4(uint32_t* r, uint32_t addr) {
    asm volatile("ldmatrix.sync.aligned.m8n8.x4.shared.b16 {%0,%1,%2,%3}, [%4];"
                 : "=r"(r[0]), "=r"(r[1]), "=r"(r[2]), "=r"(r[3]) : "r"(addr));
}
__device__ __forceinline__ void mma16816(float* d, const uint32_t* a, uint32_t b0, uint32_t b1) {
    asm volatile(
        "mma.sync.aligned.m16n8k16.row.col.f32.f16.f16.f32 "
        "{%0,%1,%2,%3}, {%4,%5,%6,%7}, {%8,%9}, {%0,%1,%2,%3};"
        : "+f"(d[0]), "+f"(d[1]), "+f"(d[2]), "+f"(d[3])
        : "r"(a[0]), "r"(a[1]), "r"(a[2]), "r"(a[3]), "r"(b0), "r"(b1));
}
__device__ __forceinline__ uint32_t h2x(float lo, float hi) {
    uint32_t r;
    asm("cvt.rn.f16x2.f32 %0, %1, %2;" : "=r"(r) : "f"(hi), "f"(lo));
    return r;
}
__device__ __forceinline__ void cpa16(uint32_t dst, const void* src) {
    asm volatile("cp.async.cg.shared.global [%0], [%1], 16;" :: "r"(dst), "l"(src));
}
__device__ __forceinline__ void cpa_commit() { asm volatile("cp.async.commit_group;"); }
template <int NWAIT>
__device__ __forceinline__ void cpa_wait() {
    asm volatile("cp.async.wait_group %0;" :: "n"(NWAIT));
}

// =====================================================================
// DCT operator + packed form
// =====================================================================
__global__ void k_dct() {
    int t = blockIdx.x, s = threadIdx.x;
    const double PI = 3.141592653589793238462643383279502884;
    double acc = 0.0;
    for (int kk = 0; kk < 16; kk++) {
        double scale = (kk == 0) ? sqrt(1.0 / 64.0) : sqrt(2.0 / 64.0);
        float ct = (float)(cos(PI * (t + 0.5) * kk / 64.0) * scale);
        float cs = (float)(cos(PI * (s + 0.5) * kk / 64.0) * scale);
        acc += (double)ct * (double)cs;
    }
    g_M[t * 64 + s] = (float)acc;
}
__global__ void k_pack() {
    int t2 = blockIdx.x, s = threadIdx.x;
    g_Mp[t2 * 64 + s] = pack2(g_M[(2 * t2) * 64 + s], g_M[(2 * t2 + 1) * 64 + s]);
}

// =====================================================================
// Merged weight split (2-way fp16)
// =====================================================================
__global__ void k_wsplit_all(const float* __restrict__ Wq, const float* __restrict__ Wk,
                             const float* __restrict__ Wv, const float* __restrict__ Wo,
                             const float* __restrict__ W1, const float* __restrict__ W2) {
    int bi = blockIdx.x;
    int tile, ob;
    if (bi < 384) { tile = bi >> 6; ob = bi & 63; }
    else { tile = 6; ob = bi - 384; }
    const float* W; int ldw, col0, K;
    switch (tile) {
        case 0: W = Wq; ldw = 128; col0 = 0;   K = 128; break;
        case 1: W = Wk; ldw = 128; col0 = 0;   K = 128; break;
        case 2: W = Wv; ldw = 128; col0 = 0;   K = 128; break;
        case 3: W = Wo; ldw = 128; col0 = 0;   K = 128; break;
        case 4: W = W1; ldw = 256; col0 = 0;   K = 128; break;
        case 5: W = W1; ldw = 256; col0 = 128; K = 128; break;
        default: W = W2; ldw = 128; col0 = 0;  K = 256; break;
    }
    __half* out = &g_wsp[tile][0];
    int idx = ob * 256 + threadIdx.x;
    int n = idx / K, k = idx - n * K;
    float w = W[(size_t)k * ldw + col0 + n];
    __half hi = __float2half_rn(w);
    float r1 = __fsub_rn(w, __half2float(hi));
    out[(size_t)(0 * 128 + n) * K + k] = hi;
    out[(size_t)(1 * 128 + n) * K + k] = __float2half_rn(r1);
}

// =====================================================================
// x -> 2 fp16 splits, pure stream
// =====================================================================
__global__ void __launch_bounds__(256) k_xsplit(const float* __restrict__ x) {
    size_t i0 = ((size_t)blockIdx.x * 256 + threadIdx.x) * 8;
    const size_t step = (size_t)gridDim.x * 256 * 8;
    for (size_t i = i0; i < TOT; i += step) {
        float4 f0 = *reinterpret_cast<const float4*>(&x[i]);
        float4 f1 = *reinterpret_cast<const float4*>(&x[i + 4]);
        float a[8] = {f0.x, f0.y, f0.z, f0.w, f1.x, f1.y, f1.z, f1.w};
        uint32_t hp[4], lp[4];
#pragma unroll
        for (int e = 0; e < 4; e++) {
            float v0 = a[2 * e], v1 = a[2 * e + 1];
            __half h0 = __float2half_rn(v0), h1 = __float2half_rn(v1);
            float r0 = __fsub_rn(v0, __half2float(h0));
            float r1 = __fsub_rn(v1, __half2float(h1));
            hp[e] = (uint32_t)*(uint16_t*)&h0 | ((uint32_t)*(uint16_t*)&h1 << 16);
            lp[e] = h2x(r0, r1);
        }
        *reinterpret_cast<uint4*>(&g_xs[0][i]) = *reinterpret_cast<uint4*>(hp);
        *reinterpret_cast<uint4*>(&g_xs[1][i]) = *reinterpret_cast<uint4*>(lp);
    }
}

// =====================================================================
// Memory mix + temporal lowpass; emits 2 fp16 splits
// =====================================================================
__global__ void __launch_bounds__(256) k_mix(const float* __restrict__ x,
                                             const float* __restrict__ mx) {
    __shared__ float s_p[64 * 128];
    __shared__ ull  s_Mp[32 * 64];
    const int bn = blockIdx.x;
    const int b = bn >> 6, n = bn & 63;
    const int tid = threadIdx.x;

    for (int i = tid; i < 2048; i += 256) s_Mp[i] = g_Mp[i];

    const float* xb = x + (size_t)(b * N_ + n) * D_;
    const float* mb = mx + ((size_t)(n * B_ + b) * T_) * D_;
    for (int i = tid; i < 8192; i += 256) {
        float mv = mb[i];
        float mv2 = __fadd_rn(__fmul_rn(0.05f, mv), __fmul_rn(0.95f, mv));
        s_p[i] = __fmul_rn(xb[(size_t)(i >> 7) * BND + (i & 127)], mv2);
    }
    __syncthreads();

    const int d = tid & 127;
    const int t2b = (tid >> 7) * 16;
    ull acc[16];
#pragma unroll
    for (int j = 0; j < 16; j++) acc[j] = 0ull;
    for (int s = 0; s < 64; s++) {
        ull cp = dup2(s_p[s * 128 + d]);
#pragma unroll
        for (int j = 0; j < 16; j++) ffma2(acc[j], s_Mp[(t2b + j) * 64 + s], cp);
    }
#pragma unroll
    for (int j = 0; j < 16; j++) {
        float2 f = *reinterpret_cast<float2*>(&acc[j]);
#pragma unroll
        for (int e = 0; e < 2; e++) {
            float v = (e == 0) ? f.x : f.y;
            size_t oi = ((size_t)(2 * (t2b + j) + e) * 4096 + bn) * 128 + d;
            __half hi = __float2half_rn(v);
            float r1 = __fsub_rn(v, __half2float(hi));
            g_ms[0][oi] = hi;
            g_ms[1][oi] = __float2half_rn(r1);
        }
    }
}

// =====================================================================
// fp16 tensor-core GEMM + fused LIF. 128 threads, 4 warps, M=64 per CTA,
// warp tile 64x32, TWO 48KB stages (double buffer), 2 CTAs/SM.
// =====================================================================
constexpr int STG = 49152;                    // 48KB per stage
constexpr int SGEMM = 1024 + 2 * STG;         // 99328; s_pre overlays stage 0
constexpr int PPAD = 130;

template <int KCHUNKS, int MODE, int NSPLITS, int NSEL>
__global__ void __launch_bounds__(128, 2) k_mmag(
    const __half* __restrict__ aspl, size_t asstride,
    const __half* __restrict__ wspA, const __half* __restrict__ wspB,
    void* __restrict__ outA, void* __restrict__ outB,
    int ldo, int ocolmul,
    const float* __restrict__ gx,
    __half* __restrict__ so0, __half* __restrict__ so1) {
    extern __shared__ __align__(16) char smem_raw[];
    const uint32_t sbase = smem_u32(smem_raw);
    float* s_pre = (float*)(smem_raw + 1024);
    const int sel = (NSEL == 2) ? (int)(blockIdx.x >> 12) : 0;
    const int bn = (NSEL == 2) ? (blockIdx.x & 4095) : blockIdx.x;
    const __half* wsp = sel ? wspB : wspA;
    void* outp = sel ? outB : outA;
    const int ocol0 = ocolmul * sel;
    const int tid = threadIdx.x;
    const int wid = tid >> 5, lane = tid & 31;
    constexpr int KTOT = KCHUNKS * 128;
    constexpr int NST = KCHUNKS * 2;

    const int n_base = wid * 32;
    const int sub = lane >> 3, lr = lane & 7;
    const int arow_off = (sub & 1) * 8 + lr;
    const int akc = (sub >> 1) * 8;
    const int brow_off = (sub >> 1) * 8 + lr;
    const int bkc = (sub & 1) * 8;

    // A tiles: 2 x 8KB (64m x 64k), B tiles: 2 x 16KB (128n x 64k)
    auto load_stage = [&](int s) {
        const int ch = s >> 1, kh = s & 1;
        const uint32_t dst = sbase + 1024 + (s & 1) * STG;
        for (int u = tid; u < NSPLITS * 512; u += 128) {
            int sp = u >> 9, r = u & 511, m = r >> 3, g = r & 7;
            const __half* src = aspl + (size_t)sp * asstride +
                ((size_t)m * 4096 + bn) * KTOT + ch * 128 + kh * 64 + g * 8;
            cpa16(dst + sp * 8192 + sw128((m << 7) + (g << 4)), src);
        }
        for (int u = tid; u < 2048; u += 128) {
            int sp = u >> 10, r = u & 1023, n = r >> 3, g = r & 7;
            const __half* src =
                wsp + ((size_t)(sp * 128 + n) * KTOT + ch * 128 + kh * 64 + g * 8);
            cpa16(dst + 16384 + sp * 16384 + sw128((n << 7) + (g << 4)), src);
        }
        cpa_commit();
    };

    float acc[4][4][4];
#pragma unroll
    for (int i = 0; i < 4; i++)
#pragma unroll
        for (int j = 0; j < 4; j++)
#pragma unroll
            for (int e = 0; e < 4; e++) acc[i][j][e] = 0.f;

    load_stage(0);
    if (NST > 1) load_stage(1);

#pragma unroll
    for (int s = 0; s < NST; s++) {
        if (s + 1 < NST) cpa_wait<1>(); else cpa_wait<0>();
        __syncthreads();

        const uint32_t Abuf = sbase + 1024 + (s & 1) * STG;
        const uint32_t Bbuf = Abuf + 16384;
        const int NP = (NSPLITS == 2) ? 3 : 2;
        const int PAs[3] = {0, 0, 1};
        const int PBs[3] = {0, 1, 0};
        const int PB1[3] = {0, 1, 0};

        for (int p = 0; p < NP; p++) {
            int As = (NSPLITS == 1) ? 0 : PAs[p];
            int Bs = (NSPLITS == 1) ? PB1[p] : PBs[p];
            uint32_t Abase = Abuf + As * 8192;
            uint32_t Bbase = Bbuf + Bs * 16384;
#pragma unroll
            for (int ks = 0; ks < 4; ks++) {
                int k0 = ks * 16;
                uint32_t afr[4][4];
#pragma unroll
                for (int mf = 0; mf < 4; mf++)
                    ldsm4(afr[mf], Abase +
                          sw128(((mf * 16 + arow_off) << 7) + (k0 + akc) * 2));
                uint32_t bfr[2][4];
#pragma unroll
                for (int nf2 = 0; nf2 < 2; nf2++)
                    ldsm4(bfr[nf2], Bbase +
                          sw128(((n_base + nf2 * 16 + brow_off) << 7) + (k0 + bkc) * 2));
#pragma unroll
                for (int mf = 0; mf < 4; mf++)
#pragma unroll
                    for (int nf = 0; nf < 4; nf++)
                        mma16816(acc[mf][nf], afr[mf],
                                 bfr[nf >> 1][(nf & 1) * 2], bfr[nf >> 1][(nf & 1) * 2 + 1]);
            }
        }
        if (s + 2 < NST) {
            __syncthreads();          // buffer (s&1) fully consumed by all warps
            load_stage(s + 2);
        }
    }
    __syncthreads();

    // ---- store fragments to s_pre (64 x 128) ----
    {
        const int qr = lane >> 2, qc = (lane & 3) * 2;
#pragma unroll
        for (int mf = 0; mf < 4; mf++)
#pragma unroll
            for (int nf = 0; nf < 4; nf++) {
                int row = mf * 16 + qr;
                int col = n_base + nf * 8 + qc;
                *reinterpret_cast<float2*>(&s_pre[row * PPAD + col]) =
                    make_float2(acc[mf][nf][0], acc[mf][nf][1]);
                *reinterpret_cast<float2*>(&s_pre[(row + 8) * PPAD + col]) =
                    make_float2(acc[mf][nf][2], acc[mf][nf][3]);
            }
    }
    __syncthreads();

    // ---- fused LIF scan: 128 threads = 128 columns ----
    {
        const int c = tid;
        float vmem = 0.f;
        const size_t ostride = (size_t)4096 * ldo;
        const size_t obase = (size_t)bn * ldo + ocol0 + c;
        const size_t gbase = (size_t)bn * 128 + c;
#pragma unroll 1
        for (int t = 0; t < 64; t++) {
            float p = s_pre[t * PPAD + c];
            vmem = __fadd_rn(vmem, __fmul_rn(__fsub_rn(p, vmem), 0.5f));
            float spk = (vmem >= 1.0f) ? 1.0f : 0.0f;
            if (vmem >= 1.0f) vmem = 0.0f;
            size_t oi = obase + (size_t)t * ostride;
            if (MODE == 0) {
                ((__half*)outp)[oi] = __float2half_rn(spk);
            } else {
                float g = gx[gbase + (size_t)t * (size_t)BND];
                float val = __fmul_rn(g, __fsub_rn(1.0f, spk));
                ((float*)outp)[oi] = val;
                if (MODE == 1) {
                    __half hi = __float2half_rn(val);
                    float r1 = __fsub_rn(val, __half2float(hi));
                    so0[oi] = hi;
                    so1[oi] = __float2half_rn(r1);
                }
            }
        }
    }
}

// =====================================================================
// Attention via tensor cores (exact fp16 in/out), emits o splits.
// =====================================================================
constexpr int ATT_Q = 0, ATT_K = 16384, ATT_V = 32768, ATT_AT = 49152;
constexpr int SATT = 65536;

__global__ void __launch_bounds__(256) k_attn3(const __half* __restrict__ q,
                                               const __half* __restrict__ k,
                                               const __half* __restrict__ v,
                                               __half* __restrict__ so0,
                                               __half* __restrict__ so1) {
    extern __shared__ __align__(16) char sm_raw[];
    const uint32_t sbase = smem_u32(sm_raw);
    const size_t base = (size_t)blockIdx.x * 8192;
    const int tid = threadIdx.x;
    const int wid = tid >> 5, lane = tid & 31;

    for (int u = tid; u < 4096; u += 256) {
        int n = u >> 6;
        int d = (u & 63) * 2;
        int h = d >> 6, dd = d & 63;
        uint32_t qp = *reinterpret_cast<const uint32_t*>(&q[base + 2 * u]);
        uint32_t kp = *reinterpret_cast<const uint32_t*>(&k[base + 2 * u]);
        uint32_t vp = *reinterpret_cast<const uint32_t*>(&v[base + 2 * u]);
        uint32_t off = sw128((n << 7) + (dd << 1));
        *reinterpret_cast<uint32_t*>(sm_raw + ATT_Q + h * 8192 + off) = qp;
        *reinterpret_cast<uint32_t*>(sm_raw + ATT_K + h * 8192 + off) = kp;
        *reinterpret_cast<uint16_t*>(sm_raw + ATT_V + h * 8192 +
            sw128((dd << 7) + (n << 1))) = (uint16_t)(vp & 0xffffu);
        *reinterpret_cast<uint16_t*>(sm_raw + ATT_V + h * 8192 +
            sw128(((dd + 1) << 7) + (n << 1))) = (uint16_t)(vp >> 16);
    }
    __syncthreads();

    const int sub = lane >> 3, lr = lane & 7;
    const int arow_off = (sub & 1) * 8 + lr;
    const int akc = (sub >> 1) * 8;
    const int brow_off = (sub >> 1) * 8 + lr;
    const int bkc = (sub & 1) * 8;
    const int qr = lane >> 2, qc = (lane & 3) * 2;

    float acc[8][4];

    {   // phase 1: attn = 0.125 * q.kT
        const int h = wid & 1;
        const int n_b = (wid >> 1) * 16;
        uint32_t Abase = sbase + ATT_Q + h * 8192;
        uint32_t Bbase = sbase + ATT_K + h * 8192;
#pragma unroll
        for (int j = 0; j < 8; j++)
#pragma unroll
            for (int e = 0; e < 4; e++) acc[j][e] = 0.f;
#pragma unroll
        for (int ks = 0; ks < 4; ks++) {
            int k0 = ks * 16;
            uint32_t afr[4];
            ldsm4(afr, Abase + sw128(((n_b + arow_off) << 7) + (k0 + akc) * 2));
#pragma unroll
            for (int mf2 = 0; mf2 < 4; mf2++) {
                uint32_t bfr[4];
                ldsm4(bfr, Bbase + sw128(((mf2 * 16 + brow_off) << 7) + (k0 + bkc) * 2));
                mma16816(acc[mf2 * 2 + 0], afr, bfr[0], bfr[1]);
                mma16816(acc[mf2 * 2 + 1], afr, bfr[2], bfr[3]);
            }
        }
        uint32_t Obase = (uint32_t)(ATT_AT + h * 8192);
#pragma unroll
        for (int j = 0; j < 8; j++) {
            int m_col = j * 8 + qc;
            int r0 = n_b + qr;
            *reinterpret_cast<uint32_t*>(sm_raw + Obase +
                sw128((r0 << 7) + m_col * 2)) = h2x(acc[j][0] * 0.125f, acc[j][1] * 0.125f);
            *reinterpret_cast<uint32_t*>(sm_raw + Obase +
                sw128(((r0 + 8) << 7) + m_col * 2)) = h2x(acc[j][2] * 0.125f, acc[j][3] * 0.125f);
        }
    }
    __syncthreads();

    {   // phase 2: o = attn . vT, emit exact 2-way fp16 splits
        const int h = wid >> 2;
        const int n_b = (wid & 3) * 16;
        uint32_t Abase = sbase + ATT_AT + h * 8192;
        uint32_t Bbase = sbase + ATT_V + h * 8192;
#pragma unroll
        for (int j = 0; j < 8; j++)
#pragma unroll
            for (int e = 0; e < 4; e++) acc[j][e] = 0.f;
#pragma unroll
        for (int ks = 0; ks < 4; ks++) {
            int k0 = ks * 16;
            uint32_t afr[4];
            ldsm4(afr, Abase + sw128(((n_b + arow_off) << 7) + (k0 + akc) * 2));
#pragma unroll
            for (int df = 0; df < 4; df++) {
                uint32_t bfr[4];
                ldsm4(bfr, Bbase + sw128(((df * 16 + brow_off) << 7) + (k0 + bkc) * 2));
                mma16816(acc[df * 2 + 0], afr, bfr[0], bfr[1]);
                mma16816(acc[df * 2 + 1], afr, bfr[2], bfr[3]);
            }
        }
#pragma unroll
        for (int j = 0; j < 8; j++) {
            int d_col = h * 64 + j * 8 + qc;
#pragma unroll
            for (int half = 0; half < 2; half++) {
                int r0 = n_b + qr + half * 8;
                float f0 = acc[j][half * 2 + 0], f1 = acc[j][half * 2 + 1];
                float h0 = __half2float(__float2half_rn(f0));
                float h1v = __half2float(__float2half_rn(f1));
                size_t oi = base + (size_t)r0 * 128 + d_col;
                *reinterpret_cast<uint32_t*>(&so0[oi]) = h2x(f0, f1);
                *reinterpret_cast<uint32_t*>(&so1[oi]) =
                    h2x(__fsub_rn(f0, h0), __fsub_rn(f1, h1v));
            }
        }
    }
}

// =====================================================================
// Host side
// =====================================================================
extern "C" void kernel_launch(void* const* d_in, const int* in_sizes, int n_in,
                              void* d_out, int out_size) {
    const float* x  = (const float*)d_in[0];
    const float* mx = (const float*)d_in[1];
    const float* Wq = (const float*)d_in[2];
    const float* Wk = (const float*)d_in[3];
    const float* Wv = (const float*)d_in[4];
    const float* Wo = (const float*)d_in[5];
    const float* W1 = (const float*)d_in[6];
    const float* W2 = (const float*)d_in[7];
    float* out = (float*)d_out;

    void *p_xs, *p_ms, *p_os, *p_xgs, *p_xg, *p_q, *p_k, *p_v, *p_h1, *p_wsp;
    cudaGetSymbolAddress(&p_xs, g_xs);
    cudaGetSymbolAddress(&p_ms, g_ms);
    cudaGetSymbolAddress(&p_os, g_os);
    cudaGetSymbolAddress(&p_xgs, g_xgs);
    cudaGetSymbolAddress(&p_xg, g_xg);
    cudaGetSymbolAddress(&p_q, g_q);
    cudaGetSymbolAddress(&p_k, g_k);
    cudaGetSymbolAddress(&p_v, g_v);
    cudaGetSymbolAddress(&p_h1, g_h1);
    cudaGetSymbolAddress(&p_wsp, g_wsp);
    __half* xs = (__half*)p_xs;
    __half* ms = (__half*)p_ms;
    __half* os = (__half*)p_os;
    __half* xgs = (__half*)p_xgs;
    __half* wsp = (__half*)p_wsp;
    const size_t WSTRIDE = 2 * 128 * 256;

    cudaFuncSetAttribute(k_mmag<1, 0, 2, 1>, cudaFuncAttributeMaxDynamicSharedMemorySize, SGEMM);
    cudaFuncSetAttribute(k_mmag<1, 0, 2, 2>, cudaFuncAttributeMaxDynamicSharedMemorySize, SGEMM);
    cudaFuncSetAttribute(k_mmag<1, 1, 2, 1>, cudaFuncAttributeMaxDynamicSharedMemorySize, SGEMM);
    cudaFuncSetAttribute(k_mmag<2, 2, 1, 1>, cudaFuncAttributeMaxDynamicSharedMemorySize, SGEMM);
    cudaFuncSetAttribute(k_attn3, cudaFuncAttributeMaxDynamicSharedMemorySize, SATT);

    k_xsplit<<<2048, 256>>>(x);                                             // 1
    k_wsplit_all<<<512, 256>>>(Wq, Wk, Wv, Wo, W1, W2);                     // 2
    k_dct<<<64, 64>>>();                                                    // 3
    // q = LIF(x @ Wq)   <- launch #4: profiled
    k_mmag<1, 0, 2, 1><<<4096, 128, SGEMM>>>(xs, TOT, wsp + 0 * WSTRIDE, nullptr,
        p_q, nullptr, 128, 0, nullptr, nullptr, nullptr);                   // 4
    k_pack<<<32, 64>>>();                                                   // 5
    k_mix<<<4096, 256>>>(x, mx);                                            // 6
    // k,v = LIF(mlp @ Wk/Wv)  fused
    k_mmag<1, 0, 2, 2><<<8192, 128, SGEMM>>>(ms, TOT, wsp + 1 * WSTRIDE,
        wsp + 2 * WSTRIDE, p_k, p_v, 128, 0, nullptr, nullptr, nullptr);    // 7
    k_attn3<<<4096, 256, SATT>>>((const __half*)p_q, (const __half*)p_k,
        (const __half*)p_v, os, os + TOT);                                  // 8
    // xg = x * (1 - LIF(o @ Wo))
    k_mmag<1, 1, 2, 1><<<4096, 128, SGEMM>>>(os, TOT, wsp + 3 * WSTRIDE, nullptr,
        p_xg, nullptr, 128, 0, x, xgs, xgs + TOT);                          // 9
    // h1 = LIF(xg @ W1) (both N-halves fused)
    k_mmag<1, 0, 2, 2><<<8192, 128, SGEMM>>>(xgs, TOT, wsp + 4 * WSTRIDE,
        wsp + 5 * WSTRIDE, p_h1, p_h1, 256, 128, nullptr, nullptr, nullptr);// 10
    // out = xg * (1 - LIF(h1 @ W2))  (binary h1 -> 1 split, K=256)
    k_mmag<2, 2, 1, 1><<<4096, 128, SGEMM>>>((const __half*)p_h1, 0,
        wsp + 6 * WSTRIDE, nullptr, out, nullptr, 128, 0, (const float*)p_xg,
        nullptr, nullptr);                                                  // 11
}

// round 13
// speedup vs baseline: 1.0487x; 1.0487x over previous
#include <cuda_runtime.h>
#include <cuda_bf16.h>
#include <cuda_fp16.h>
#include <cstdint>

typedef unsigned long long ull;

constexpr int T_ = 64, B_ = 64, N_ = 64, D_ = 128, HID_ = 256;
constexpr int BND = B_ * N_ * D_;                      // 524288
constexpr size_t TOT  = (size_t)T_ * BND;              // 33554432
constexpr size_t TOTH = (size_t)T_ * B_ * N_ * HID_;   // 67108864

// -------- scratch --------
__device__ ull   g_Mp[32 * 64];
__device__ __half g_xs[2][TOT];
__device__ __half g_ms[2][TOT];
__device__ __half g_os[2][TOT];
__device__ __half g_xgs[2][TOT];
__device__ float  g_xg[TOT];
__device__ __half g_q[TOT];
__device__ __half g_k[TOT];
__device__ __half g_v[TOT];
__device__ __half g_h1[TOTH];
__device__ __half g_wsp[7][2 * 128 * 256];

// -------- helpers --------
__device__ __forceinline__ void ffma2(ull& d, ull a, ull b) {
    asm("fma.rn.f32x2 %0, %1, %2, %0;" : "+l"(d) : "l"(a), "l"(b));
}
__device__ __forceinline__ ull dup2(float x) {
    ull r; unsigned u = __float_as_uint(x);
    asm("mov.b64 %0, {%1, %1};" : "=l"(r) : "r"(u));
    return r;
}
__device__ __forceinline__ ull pack2(float lo, float hi) {
    ull r;
    asm("mov.b64 %0, {%1, %2};" : "=l"(r) : "r"(__float_as_uint(lo)), "r"(__float_as_uint(hi)));
    return r;
}
__device__ __forceinline__ uint32_t smem_u32(const void* p) {
    uint32_t a;
    asm("{ .reg .u64 t; cvta.to.shared.u64 t, %1; cvt.u32.u64 %0, t; }" : "=r"(a) : "l"(p));
    return a;
}
__device__ __forceinline__ uint32_t sw128(uint32_t off) { return off ^ ((off >> 3) & 0x70); }
__device__ __forceinline__ void ldsm4(uint32_t* r, uint32_t addr) {
    asm volatile("ldmatrix.sync.aligned.m8n8.x4.shared.b16 {%0,%1,%2,%3}, [%4];"
                 : "=r"(r[0]), "=r"(r[1]), "=r"(r[2]), "=r"(r[3]) : "r"(addr));
}
__device__ __forceinline__ void mma16816(float* d, const uint32_t* a, uint32_t b0, uint32_t b1) {
    asm volatile(
        "mma.sync.aligned.m16n8k16.row.col.f32.f16.f16.f32 "
        "{%0,%1,%2,%3}, {%4,%5,%6,%7}, {%8,%9}, {%0,%1,%2,%3};"
        : "+f"(d[0]), "+f"(d[1]), "+f"(d[2]), "+f"(d[3])
        : "r"(a[0]), "r"(a[1]), "r"(a[2]), "r"(a[3]), "r"(b0), "r"(b1));
}
__device__ __forceinline__ uint32_t h2x(float lo, float hi) {
    uint32_t r;
    asm("cvt.rn.f16x2.f32 %0, %1, %2;" : "=r"(r) : "f"(hi), "f"(lo));
    return r;
}
__device__ __forceinline__ void cpa16(uint32_t dst, const void* src) {
    asm volatile("cp.async.cg.shared.global [%0], [%1], 16;" :: "r"(dst), "l"(src));
}
__device__ __forceinline__ void cpa_commit() { asm volatile("cp.async.commit_group;"); }
template <int NWAIT>
__device__ __forceinline__ void cpa_wait() {
    asm volatile("cp.async.wait_group %0;" :: "n"(NWAIT));
}

// =====================================================================
// Prep kernel: xsplit (blocks 0..2047) + wsplit (2048..2559) + dct-pack
// (2560..2567). 256 threads.
// =====================================================================
__global__ void __launch_bounds__(256) k_prep(
    const float* __restrict__ x,
    const float* __restrict__ Wq, const float* __restrict__ Wk,
    const float* __restrict__ Wv, const float* __restrict__ Wo,
    const float* __restrict__ W1, const float* __restrict__ W2) {
    const int bi = blockIdx.x;
    const int tid = threadIdx.x;
    if (bi < 2048) {
        // ---- x -> 2 fp16 splits ----
        size_t i0 = ((size_t)bi * 256 + tid) * 8;
        const size_t step = (size_t)2048 * 256 * 8;
        for (size_t i = i0; i < TOT; i += step) {
            float4 f0 = *reinterpret_cast<const float4*>(&x[i]);
            float4 f1 = *reinterpret_cast<const float4*>(&x[i + 4]);
            float a[8] = {f0.x, f0.y, f0.z, f0.w, f1.x, f1.y, f1.z, f1.w};
            uint32_t hp[4], lp[4];
#pragma unroll
            for (int e = 0; e < 4; e++) {
                float v0 = a[2 * e], v1 = a[2 * e + 1];
                __half h0 = __float2half_rn(v0), h1 = __float2half_rn(v1);
                float r0 = __fsub_rn(v0, __half2float(h0));
                float r1 = __fsub_rn(v1, __half2float(h1));
                hp[e] = (uint32_t)*(uint16_t*)&h0 | ((uint32_t)*(uint16_t*)&h1 << 16);
                lp[e] = h2x(r0, r1);
            }
            *reinterpret_cast<uint4*>(&g_xs[0][i]) = *reinterpret_cast<uint4*>(hp);
            *reinterpret_cast<uint4*>(&g_xs[1][i]) = *reinterpret_cast<uint4*>(lp);
        }
    } else if (bi < 2560) {
        // ---- weight 2-way fp16 splits ----
        int wbi = bi - 2048;
        int tile, ob;
        if (wbi < 384) { tile = wbi >> 6; ob = wbi & 63; }
        else { tile = 6; ob = wbi - 384; }
        const float* W; int ldw, col0, K;
        switch (tile) {
            case 0: W = Wq; ldw = 128; col0 = 0;   K = 128; break;
            case 1: W = Wk; ldw = 128; col0 = 0;   K = 128; break;
            case 2: W = Wv; ldw = 128; col0 = 0;   K = 128; break;
            case 3: W = Wo; ldw = 128; col0 = 0;   K = 128; break;
            case 4: W = W1; ldw = 256; col0 = 0;   K = 128; break;
            case 5: W = W1; ldw = 256; col0 = 128; K = 128; break;
            default: W = W2; ldw = 128; col0 = 0;  K = 256; break;
        }
        __half* out = &g_wsp[tile][0];
        int idx = ob * 256 + tid;
        int n = idx / K, k = idx - n * K;
        float w = W[(size_t)k * ldw + col0 + n];
        __half hi = __float2half_rn(w);
        float r1 = __fsub_rn(w, __half2float(hi));
        out[(size_t)(0 * 128 + n) * K + k] = hi;
        out[(size_t)(1 * 128 + n) * K + k] = __float2half_rn(r1);
    } else {
        // ---- DCT lowpass operator, packed pairs: Mp[t2*64+s] ----
        int idx = (bi - 2560) * 256 + tid;     // [0, 2048)
        int t2 = idx >> 6, s = idx & 63;
        const double PI = 3.141592653589793238462643383279502884;
        float rows[2];
#pragma unroll
        for (int e = 0; e < 2; e++) {
            int t = 2 * t2 + e;
            double acc = 0.0;
            for (int kk = 0; kk < 16; kk++) {
                double scale = (kk == 0) ? sqrt(1.0 / 64.0) : sqrt(2.0 / 64.0);
                float ct = (float)(cos(PI * (t + 0.5) * kk / 64.0) * scale);
                float cs = (float)(cos(PI * (s + 0.5) * kk / 64.0) * scale);
                acc += (double)ct * (double)cs;
            }
            rows[e] = (float)acc;
        }
        g_Mp[t2 * 64 + s] = pack2(rows[0], rows[1]);
    }
}

// =====================================================================
// GEMM tile device function (round-11 config: M=64 tile, 4 warps,
// single 48KB stage, fused LIF epilogue)
// =====================================================================
constexpr int SGEMM = 1024 + 48 * 1024;   // 50176
constexpr int PPAD = 130;

template <int KCHUNKS, int MODE, int NSPLITS>
__device__ __forceinline__ void gemm_tile(
    int bn, const __half* __restrict__ aspl, size_t asstride,
    const __half* __restrict__ wsp,
    void* __restrict__ outp, int ldo, int ocol0,
    const float* __restrict__ gx,
    __half* __restrict__ so0, __half* __restrict__ so1,
    char* smem_raw) {
    const uint32_t sbase = smem_u32(smem_raw);
    float* s_pre = (float*)(smem_raw + 1024);
    const int tid = threadIdx.x;
    const int wid = tid >> 5, lane = tid & 31;
    constexpr int KTOT = KCHUNKS * 128;
    constexpr int NST = KCHUNKS * 2;

    const int n_base = wid * 32;
    const int sub = lane >> 3, lr = lane & 7;
    const int arow_off = (sub & 1) * 8 + lr;
    const int akc = (sub >> 1) * 8;
    const int brow_off = (sub >> 1) * 8 + lr;
    const int bkc = (sub & 1) * 8;

    float acc[4][4][4];
#pragma unroll
    for (int i = 0; i < 4; i++)
#pragma unroll
        for (int j = 0; j < 4; j++)
#pragma unroll
            for (int e = 0; e < 4; e++) acc[i][j][e] = 0.f;

#pragma unroll
    for (int s = 0; s < NST; s++) {
        if (s) __syncthreads();
        {   // load stage s
            const int ch = s >> 1, kh = s & 1;
            const uint32_t dst = sbase + 1024;
            for (int u = tid; u < NSPLITS * 512; u += 128) {
                int sp = u >> 9, r = u & 511, m = r >> 3, g = r & 7;
                const __half* src = aspl + (size_t)sp * asstride +
                    ((size_t)m * 4096 + bn) * KTOT + ch * 128 + kh * 64 + g * 8;
                cpa16(dst + sp * 8192 + sw128((m << 7) + (g << 4)), src);
            }
            for (int u = tid; u < 2048; u += 128) {
                int sp = u >> 10, r = u & 1023, n = r >> 3, g = r & 7;
                const __half* src =
                    wsp + ((size_t)(sp * 128 + n) * KTOT + ch * 128 + kh * 64 + g * 8);
                cpa16(dst + 16384 + sp * 16384 + sw128((n << 7) + (g << 4)), src);
            }
            cpa_commit();
        }
        cpa_wait<0>();
        __syncthreads();

        const uint32_t Abuf = sbase + 1024;
        const uint32_t Bbuf = Abuf + 16384;
        const int NP = (NSPLITS == 2) ? 3 : 2;
        const int PAs[3] = {0, 0, 1};
        const int PBs[3] = {0, 1, 0};
        const int PB1[3] = {0, 1, 0};

        for (int p = 0; p < NP; p++) {
            int As = (NSPLITS == 1) ? 0 : PAs[p];
            int Bs = (NSPLITS == 1) ? PB1[p] : PBs[p];
            uint32_t Abase = Abuf + As * 8192;
            uint32_t Bbase = Bbuf + Bs * 16384;
#pragma unroll
            for (int ks = 0; ks < 4; ks++) {
                int k0 = ks * 16;
                uint32_t afr[4][4];
#pragma unroll
                for (int mf = 0; mf < 4; mf++)
                    ldsm4(afr[mf], Abase +
                          sw128(((mf * 16 + arow_off) << 7) + (k0 + akc) * 2));
                uint32_t bfr[2][4];
#pragma unroll
                for (int nf2 = 0; nf2 < 2; nf2++)
                    ldsm4(bfr[nf2], Bbase +
                          sw128(((n_base + nf2 * 16 + brow_off) << 7) + (k0 + bkc) * 2));
#pragma unroll
                for (int mf = 0; mf < 4; mf++)
#pragma unroll
                    for (int nf = 0; nf < 4; nf++)
                        mma16816(acc[mf][nf], afr[mf],
                                 bfr[nf >> 1][(nf & 1) * 2], bfr[nf >> 1][(nf & 1) * 2 + 1]);
            }
        }
    }
    __syncthreads();

    {   // store fragments to s_pre (64 x 128)
        const int qr = lane >> 2, qc = (lane & 3) * 2;
#pragma unroll
        for (int mf = 0; mf < 4; mf++)
#pragma unroll
            for (int nf = 0; nf < 4; nf++) {
                int row = mf * 16 + qr;
                int col = n_base + nf * 8 + qc;
                *reinterpret_cast<float2*>(&s_pre[row * PPAD + col]) =
                    make_float2(acc[mf][nf][0], acc[mf][nf][1]);
                *reinterpret_cast<float2*>(&s_pre[(row + 8) * PPAD + col]) =
                    make_float2(acc[mf][nf][2], acc[mf][nf][3]);
            }
    }
    __syncthreads();

    {   // fused LIF scan: 128 threads = 128 columns
        const int c = tid;
        float vmem = 0.f;
        const size_t ostride = (size_t)4096 * ldo;
        const size_t obase = (size_t)bn * ldo + ocol0 + c;
        const size_t gbase = (size_t)bn * 128 + c;
#pragma unroll 1
        for (int t = 0; t < 64; t++) {
            float p = s_pre[t * PPAD + c];
            vmem = __fadd_rn(vmem, __fmul_rn(__fsub_rn(p, vmem), 0.5f));
            float spk = (vmem >= 1.0f) ? 1.0f : 0.0f;
            if (vmem >= 1.0f) vmem = 0.0f;
            size_t oi = obase + (size_t)t * ostride;
            if (MODE == 0) {
                ((__half*)outp)[oi] = __float2half_rn(spk);
            } else {
                float g = gx[gbase + (size_t)t * (size_t)BND];
                float val = __fmul_rn(g, __fsub_rn(1.0f, spk));
                ((float*)outp)[oi] = val;
                if (MODE == 1) {
                    __half hi = __float2half_rn(val);
                    float r1 = __fsub_rn(val, __half2float(hi));
                    so0[oi] = hi;
                    so1[oi] = __float2half_rn(r1);
                }
            }
        }
    }
}

// =====================================================================
// Mix tile device function (128 threads, dynamic smem)
// =====================================================================
__device__ __forceinline__ void mix_tile(int bn, const float* __restrict__ x,
                                         const float* __restrict__ mx,
                                         char* smem_raw) {
    float* s_p = (float*)smem_raw;                  // 32 KB
    ull* s_Mp = (ull*)(smem_raw + 32768);           // 16 KB
    const int b = bn >> 6, n = bn & 63;
    const int tid = threadIdx.x;

    for (int i = tid; i < 2048; i += 128) s_Mp[i] = g_Mp[i];

    const float* xb = x + (size_t)(b * N_ + n) * D_;
    const float* mb = mx + ((size_t)(n * B_ + b) * T_) * D_;
    for (int i = tid; i < 8192; i += 128) {
        float mv = mb[i];
        float mv2 = __fadd_rn(__fmul_rn(0.05f, mv), __fmul_rn(0.95f, mv));
        s_p[i] = __fmul_rn(xb[(size_t)(i >> 7) * BND + (i & 127)], mv2);
    }
    __syncthreads();

    const int d = tid;
    ull acc[32];
#pragma unroll
    for (int j = 0; j < 32; j++) acc[j] = 0ull;
    for (int s = 0; s < 64; s++) {
        ull cp = dup2(s_p[s * 128 + d]);
#pragma unroll
        for (int j = 0; j < 32; j++) ffma2(acc[j], s_Mp[j * 64 + s], cp);
    }
#pragma unroll
    for (int j = 0; j < 32; j++) {
        float2 f = *reinterpret_cast<float2*>(&acc[j]);
#pragma unroll
        for (int e = 0; e < 2; e++) {
            float v = (e == 0) ? f.x : f.y;
            size_t oi = ((size_t)(2 * j + e) * 4096 + bn) * 128 + d;
            __half hi = __float2half_rn(v);
            float r1 = __fsub_rn(v, __half2float(hi));
            g_ms[0][oi] = hi;
            g_ms[1][oi] = __float2half_rn(r1);
        }
    }
}

// =====================================================================
// Combo kernel: blocks [0,4096) = q-GEMM, [4096,8192) = mix
// =====================================================================
__global__ void __launch_bounds__(128, 4) k_combo(
    const __half* __restrict__ xs0, const __half* __restrict__ wspq,
    __half* __restrict__ qout,
    const float* __restrict__ x, const float* __restrict__ mx) {
    extern __shared__ __align__(16) char smem_raw[];
    if (blockIdx.x < 4096) {
        gemm_tile<1, 0, 2>(blockIdx.x, xs0, TOT, wspq, qout, 128, 0,
                           nullptr, nullptr, nullptr, smem_raw);
    } else {
        mix_tile(blockIdx.x - 4096, x, mx, smem_raw);
    }
}

// =====================================================================
// Standalone GEMM kernel (NSEL fan-out)
// =====================================================================
template <int KCHUNKS, int MODE, int NSPLITS, int NSEL>
__global__ void __launch_bounds__(128, 4) k_mmag(
    const __half* __restrict__ aspl, size_t asstride,
    const __half* __restrict__ wspA, const __half* __restrict__ wspB,
    void* __restrict__ outA, void* __restrict__ outB,
    int ldo, int ocolmul,
    const float* __restrict__ gx,
    __half* __restrict__ so0, __half* __restrict__ so1) {
    extern __shared__ __align__(16) char smem_raw[];
    const int sel = (NSEL == 2) ? (int)(blockIdx.x >> 12) : 0;
    const int bn = (NSEL == 2) ? (blockIdx.x & 4095) : blockIdx.x;
    gemm_tile<KCHUNKS, MODE, NSPLITS>(bn, aspl, asstride,
        sel ? wspB : wspA, sel ? outB : outA, ldo, ocolmul * sel,
        gx, so0, so1, smem_raw);
}

// =====================================================================
// Attention via tensor cores (exact fp16 in/out), emits o splits.
// =====================================================================
constexpr int ATT_Q = 0, ATT_K = 16384, ATT_V = 32768, ATT_AT = 49152;
constexpr int SATT = 65536;

__global__ void __launch_bounds__(256) k_attn3(const __half* __restrict__ q,
                                               const __half* __restrict__ k,
                                               const __half* __restrict__ v,
                                               __half* __restrict__ so0,
                                               __half* __restrict__ so1) {
    extern __shared__ __align__(16) char sm_raw[];
    const uint32_t sbase = smem_u32(sm_raw);
    const size_t base = (size_t)blockIdx.x * 8192;
    const int tid = threadIdx.x;
    const int wid = tid >> 5, lane = tid & 31;

    for (int u = tid; u < 4096; u += 256) {
        int n = u >> 6;
        int d = (u & 63) * 2;
        int h = d >> 6, dd = d & 63;
        uint32_t qp = *reinterpret_cast<const uint32_t*>(&q[base + 2 * u]);
        uint32_t kp = *reinterpret_cast<const uint32_t*>(&k[base + 2 * u]);
        uint32_t vp = *reinterpret_cast<const uint32_t*>(&v[base + 2 * u]);
        uint32_t off = sw128((n << 7) + (dd << 1));
        *reinterpret_cast<uint32_t*>(sm_raw + ATT_Q + h * 8192 + off) = qp;
        *reinterpret_cast<uint32_t*>(sm_raw + ATT_K + h * 8192 + off) = kp;
        *reinterpret_cast<uint16_t*>(sm_raw + ATT_V + h * 8192 +
            sw128((dd << 7) + (n << 1))) = (uint16_t)(vp & 0xffffu);
        *reinterpret_cast<uint16_t*>(sm_raw + ATT_V + h * 8192 +
            sw128(((dd + 1) << 7) + (n << 1))) = (uint16_t)(vp >> 16);
    }
    __syncthreads();

    const int sub = lane >> 3, lr = lane & 7;
    const int arow_off = (sub & 1) * 8 + lr;
    const int akc = (sub >> 1) * 8;
    const int brow_off = (sub >> 1) * 8 + lr;
    const int bkc = (sub & 1) * 8;
    const int qr = lane >> 2, qc = (lane & 3) * 2;

    float acc[8][4];

    {   // phase 1: attn = 0.125 * q.kT
        const int h = wid & 1;
        const int n_b = (wid >> 1) * 16;
        uint32_t Abase = sbase + ATT_Q + h * 8192;
        uint32_t Bbase = sbase + ATT_K + h * 8192;
#pragma unroll
        for (int j = 0; j < 8; j++)
#pragma unroll
            for (int e = 0; e < 4; e++) acc[j][e] = 0.f;
#pragma unroll
        for (int ks = 0; ks < 4; ks++) {
            int k0 = ks * 16;
            uint32_t afr[4];
            ldsm4(afr, Abase + sw128(((n_b + arow_off) << 7) + (k0 + akc) * 2));
#pragma unroll
            for (int mf2 = 0; mf2 < 4; mf2++) {
                uint32_t bfr[4];
                ldsm4(bfr, Bbase + sw128(((mf2 * 16 + brow_off) << 7) + (k0 + bkc) * 2));
                mma16816(acc[mf2 * 2 + 0], afr, bfr[0], bfr[1]);
                mma16816(acc[mf2 * 2 + 1], afr, bfr[2], bfr[3]);
            }
        }
        uint32_t Obase = (uint32_t)(ATT_AT + h * 8192);
#pragma unroll
        for (int j = 0; j < 8; j++) {
            int m_col = j * 8 + qc;
            int r0 = n_b + qr;
            *reinterpret_cast<uint32_t*>(sm_raw + Obase +
                sw128((r0 << 7) + m_col * 2)) = h2x(acc[j][0] * 0.125f, acc[j][1] * 0.125f);
            *reinterpret_cast<uint32_t*>(sm_raw + Obase +
                sw128(((r0 + 8) << 7) + m_col * 2)) = h2x(acc[j][2] * 0.125f, acc[j][3] * 0.125f);
        }
    }
    __syncthreads();

    {   // phase 2: o = attn . vT, emit exact 2-way fp16 splits
        const int h = wid >> 2;
        const int n_b = (wid & 3) * 16;
        uint32_t Abase = sbase + ATT_AT + h * 8192;
        uint32_t Bbase = sbase + ATT_V + h * 8192;
#pragma unroll
        for (int j = 0; j < 8; j++)
#pragma unroll
            for (int e = 0; e < 4; e++) acc[j][e] = 0.f;
#pragma unroll
        for (int ks = 0; ks < 4; ks++) {
            int k0 = ks * 16;
            uint32_t afr[4];
            ldsm4(afr, Abase + sw128(((n_b + arow_off) << 7) + (k0 + akc) * 2));
#pragma unroll
            for (int df = 0; df < 4; df++) {
                uint32_t bfr[4];
                ldsm4(bfr, Bbase + sw128(((df * 16 + brow_off) << 7) + (k0 + bkc) * 2));
                mma16816(acc[df * 2 + 0], afr, bfr[0], bfr[1]);
                mma16816(acc[df * 2 + 1], afr, bfr[2], bfr[3]);
            }
        }
#pragma unroll
        for (int j = 0; j < 8; j++) {
            int d_col = h * 64 + j * 8 + qc;
#pragma unroll
            for (int half = 0; half < 2; half++) {
                int r0 = n_b + qr + half * 8;
                float f0 = acc[j][half * 2 + 0], f1 = acc[j][half * 2 + 1];
                float h0 = __half2float(__float2half_rn(f0));
                float h1v = __half2float(__float2half_rn(f1));
                size_t oi = base + (size_t)r0 * 128 + d_col;
                *reinterpret_cast<uint32_t*>(&so0[oi]) = h2x(f0, f1);
                *reinterpret_cast<uint32_t*>(&so1[oi]) =
                    h2x(__fsub_rn(f0, h0), __fsub_rn(f1, h1v));
            }
        }
    }
}

// =====================================================================
// Host side
// =====================================================================
extern "C" void kernel_launch(void* const* d_in, const int* in_sizes, int n_in,
                              void* d_out, int out_size) {
    const float* x  = (const float*)d_in[0];
    const float* mx = (const float*)d_in[1];
    const float* Wq = (const float*)d_in[2];
    const float* Wk = (const float*)d_in[3];
    const float* Wv = (const float*)d_in[4];
    const float* Wo = (const float*)d_in[5];
    const float* W1 = (const float*)d_in[6];
    const float* W2 = (const float*)d_in[7];
    float* out = (float*)d_out;

    void *p_xs, *p_ms, *p_os, *p_xgs, *p_xg, *p_q, *p_k, *p_v, *p_h1, *p_wsp;
    cudaGetSymbolAddress(&p_xs, g_xs);
    cudaGetSymbolAddress(&p_ms, g_ms);
    cudaGetSymbolAddress(&p_os, g_os);
    cudaGetSymbolAddress(&p_xgs, g_xgs);
    cudaGetSymbolAddress(&p_xg, g_xg);
    cudaGetSymbolAddress(&p_q, g_q);
    cudaGetSymbolAddress(&p_k, g_k);
    cudaGetSymbolAddress(&p_v, g_v);
    cudaGetSymbolAddress(&p_h1, g_h1);
    cudaGetSymbolAddress(&p_wsp, g_wsp);
    __half* xs = (__half*)p_xs;
    __half* ms = (__half*)p_ms;
    __half* os = (__half*)p_os;
    __half* xgs = (__half*)p_xgs;
    __half* wsp = (__half*)p_wsp;
    const size_t WSTRIDE = 2 * 128 * 256;

    cudaFuncSetAttribute(k_combo, cudaFuncAttributeMaxDynamicSharedMemorySize, SGEMM);
    cudaFuncSetAttribute(k_mmag<1, 0, 2, 2>, cudaFuncAttributeMaxDynamicSharedMemorySize, SGEMM);
    cudaFuncSetAttribute(k_mmag<1, 1, 2, 1>, cudaFuncAttributeMaxDynamicSharedMemorySize, SGEMM);
    cudaFuncSetAttribute(k_mmag<2, 2, 1, 1>, cudaFuncAttributeMaxDynamicSharedMemorySize, SGEMM);
    cudaFuncSetAttribute(k_attn3, cudaFuncAttributeMaxDynamicSharedMemorySize, SATT);

    // 1: prep (xsplit + wsplit + dct-pack)
    k_prep<<<2568, 256>>>(x, Wq, Wk, Wv, Wo, W1, W2);
    // 2: combo — q = LIF(x @ Wq) overlapped with mix (mlp splits)
    k_combo<<<8192, 128, SGEMM>>>(xs, wsp + 0 * WSTRIDE, (__half*)p_q, x, mx);
    // 3: k,v = LIF(mlp @ Wk/Wv)  fused
    k_mmag<1, 0, 2, 2><<<8192, 128, SGEMM>>>(ms, TOT, wsp + 1 * WSTRIDE,
        wsp + 2 * WSTRIDE, p_k, p_v, 128, 0, nullptr, nullptr, nullptr);
    // 4: attention  <- profiled
    k_attn3<<<4096, 256, SATT>>>((const __half*)p_q, (const __half*)p_k,
        (const __half*)p_v, os, os + TOT);
    // 5: xg = x * (1 - LIF(o @ Wo))
    k_mmag<1, 1, 2, 1><<<4096, 128, SGEMM>>>(os, TOT, wsp + 3 * WSTRIDE, nullptr,
        p_xg, nullptr, 128, 0, x, xgs, xgs + TOT);
    // 6: h1 = LIF(xg @ W1) (both N-halves fused)
    k_mmag<1, 0, 2, 2><<<8192, 128, SGEMM>>>(xgs, TOT, wsp + 4 * WSTRIDE,
        wsp + 5 * WSTRIDE, p_h1, p_h1, 256, 128, nullptr, nullptr, nullptr);
    // 7: out = xg * (1 - LIF(h1 @ W2))
    k_mmag<2, 2, 1, 1><<<4096, 128, SGEMM>>>((const __half*)p_h1, 0,
        wsp + 6 * WSTRIDE, nullptr, out, nullptr, 128, 0, (const float*)p_xg,
        nullptr, nullptr);
}

// round 14
// speedup vs baseline: 1.0950x; 1.0442x over previous
#include <cuda_runtime.h>
#include <cuda_bf16.h>
#include <cuda_fp16.h>
#include <cstdint>

typedef unsigned long long ull;

constexpr int T_ = 64, B_ = 64, N_ = 64, D_ = 128, HID_ = 256;
constexpr int BND = B_ * N_ * D_;                      // 524288
constexpr size_t TOT  = (size_t)T_ * BND;              // 33554432
constexpr size_t TOTH = (size_t)T_ * B_ * N_ * HID_;   // 67108864

// -------- scratch --------
__device__ ull    g_Mp[32 * 64];
__device__ __half g_xs[2][TOT];
__device__ __half g_ms[2][TOT];
__device__ __half g_os[2][TOT];
__device__ __half g_xgs[2][TOT];
__device__ float  g_xg[TOT];
__device__ uint32_t g_qm[(size_t)T_ * 4096 * 4];   // spike masks: 4 words/(t,bn)
__device__ uint32_t g_km[(size_t)T_ * 4096 * 4];
__device__ __half g_v[TOT];
__device__ __half g_h1[TOTH];
__device__ __half g_wsp[7][2 * 128 * 256];

// -------- helpers --------
__device__ __forceinline__ void ffma2(ull& d, ull a, ull b) {
    asm("fma.rn.f32x2 %0, %1, %2, %0;" : "+l"(d) : "l"(a), "l"(b));
}
__device__ __forceinline__ ull dup2(float x) {
    ull r; unsigned u = __float_as_uint(x);
    asm("mov.b64 %0, {%1, %1};" : "=l"(r) : "r"(u));
    return r;
}
__device__ __forceinline__ ull pack2(float lo, float hi) {
    ull r;
    asm("mov.b64 %0, {%1, %2};" : "=l"(r) : "r"(__float_as_uint(lo)), "r"(__float_as_uint(hi)));
    return r;
}
__device__ __forceinline__ uint32_t smem_u32(const void* p) {
    uint32_t a;
    asm("{ .reg .u64 t; cvta.to.shared.u64 t, %1; cvt.u32.u64 %0, t; }" : "=r"(a) : "l"(p));
    return a;
}
__device__ __forceinline__ uint32_t sw128(uint32_t off) { return off ^ ((off >> 3) & 0x70); }
__device__ __forceinline__ void ldsm4(uint32_t* r, uint32_t addr) {
    asm volatile("ldmatrix.sync.aligned.m8n8.x4.shared.b16 {%0,%1,%2,%3}, [%4];"
                 : "=r"(r[0]), "=r"(r[1]), "=r"(r[2]), "=r"(r[3]) : "r"(addr));
}
__device__ __forceinline__ void mma16816(float* d, const uint32_t* a, uint32_t b0, uint32_t b1) {
    asm volatile(
        "mma.sync.aligned.m16n8k16.row.col.f32.f16.f16.f32 "
        "{%0,%1,%2,%3}, {%4,%5,%6,%7}, {%8,%9}, {%0,%1,%2,%3};"
        : "+f"(d[0]), "+f"(d[1]), "+f"(d[2]), "+f"(d[3])
        : "r"(a[0]), "r"(a[1]), "r"(a[2]), "r"(a[3]), "r"(b0), "r"(b1));
}
__device__ __forceinline__ uint32_t h2x(float lo, float hi) {
    uint32_t r;
    asm("cvt.rn.f16x2.f32 %0, %1, %2;" : "=r"(r) : "f"(hi), "f"(lo));
    return r;
}
__device__ __forceinline__ void cpa16(uint32_t dst, const void* src) {
    asm volatile("cp.async.cg.shared.global [%0], [%1], 16;" :: "r"(dst), "l"(src));
}
__device__ __forceinline__ void cpa_commit() { asm volatile("cp.async.commit_group;"); }
template <int NWAIT>
__device__ __forceinline__ void cpa_wait() {
    asm volatile("cp.async.wait_group %0;" :: "n"(NWAIT));
}

// =====================================================================
// Prep kernel: xsplit (0..2047) + wsplit (2048..2559) + dct-pack (2560..2567)
// =====================================================================
__global__ void __launch_bounds__(256) k_prep(
    const float* __restrict__ x,
    const float* __restrict__ Wq, const float* __restrict__ Wk,
    const float* __restrict__ Wv, const float* __restrict__ Wo,
    const float* __restrict__ W1, const float* __restrict__ W2) {
    const int bi = blockIdx.x;
    const int tid = threadIdx.x;
    if (bi < 2048) {
        size_t i0 = ((size_t)bi * 256 + tid) * 8;
        const size_t step = (size_t)2048 * 256 * 8;
        for (size_t i = i0; i < TOT; i += step) {
            float4 f0 = *reinterpret_cast<const float4*>(&x[i]);
            float4 f1 = *reinterpret_cast<const float4*>(&x[i + 4]);
            float a[8] = {f0.x, f0.y, f0.z, f0.w, f1.x, f1.y, f1.z, f1.w};
            uint32_t hp[4], lp[4];
#pragma unroll
            for (int e = 0; e < 4; e++) {
                float v0 = a[2 * e], v1 = a[2 * e + 1];
                __half h0 = __float2half_rn(v0), h1 = __float2half_rn(v1);
                float r0 = __fsub_rn(v0, __half2float(h0));
                float r1 = __fsub_rn(v1, __half2float(h1));
                hp[e] = (uint32_t)*(uint16_t*)&h0 | ((uint32_t)*(uint16_t*)&h1 << 16);
                lp[e] = h2x(r0, r1);
            }
            *reinterpret_cast<uint4*>(&g_xs[0][i]) = *reinterpret_cast<uint4*>(hp);
            *reinterpret_cast<uint4*>(&g_xs[1][i]) = *reinterpret_cast<uint4*>(lp);
        }
    } else if (bi < 2560) {
        int wbi = bi - 2048;
        int tile, ob;
        if (wbi < 384) { tile = wbi >> 6; ob = wbi & 63; }
        else { tile = 6; ob = wbi - 384; }
        const float* W; int ldw, col0, K;
        switch (tile) {
            case 0: W = Wq; ldw = 128; col0 = 0;   K = 128; break;
            case 1: W = Wk; ldw = 128; col0 = 0;   K = 128; break;
            case 2: W = Wv; ldw = 128; col0 = 0;   K = 128; break;
            case 3: W = Wo; ldw = 128; col0 = 0;   K = 128; break;
            case 4: W = W1; ldw = 256; col0 = 0;   K = 128; break;
            case 5: W = W1; ldw = 256; col0 = 128; K = 128; break;
            default: W = W2; ldw = 128; col0 = 0;  K = 256; break;
        }
        __half* out = &g_wsp[tile][0];
        int idx = ob * 256 + tid;
        int n = idx / K, k = idx - n * K;
        float w = W[(size_t)k * ldw + col0 + n];
        __half hi = __float2half_rn(w);
        float r1 = __fsub_rn(w, __half2float(hi));
        out[(size_t)(0 * 128 + n) * K + k] = hi;
        out[(size_t)(1 * 128 + n) * K + k] = __float2half_rn(r1);
    } else {
        int idx = (bi - 2560) * 256 + tid;
        int t2 = idx >> 6, s = idx & 63;
        const double PI = 3.141592653589793238462643383279502884;
        float rows[2];
#pragma unroll
        for (int e = 0; e < 2; e++) {
            int t = 2 * t2 + e;
            double acc = 0.0;
            for (int kk = 0; kk < 16; kk++) {
                double scale = (kk == 0) ? sqrt(1.0 / 64.0) : sqrt(2.0 / 64.0);
                float ct = (float)(cos(PI * (t + 0.5) * kk / 64.0) * scale);
                float cs = (float)(cos(PI * (s + 0.5) * kk / 64.0) * scale);
                acc += (double)ct * (double)cs;
            }
            rows[e] = (float)acc;
        }
        g_Mp[t2 * 64 + s] = pack2(rows[0], rows[1]);
    }
}

// =====================================================================
// Memory mix + temporal lowpass (round-11 standalone, 256 threads)
// =====================================================================
__global__ void __launch_bounds__(256) k_mix(const float* __restrict__ x,
                                             const float* __restrict__ mx) {
    __shared__ float s_p[64 * 128];
    __shared__ ull  s_Mp[32 * 64];
    const int bn = blockIdx.x;
    const int b = bn >> 6, n = bn & 63;
    const int tid = threadIdx.x;

    for (int i = tid; i < 2048; i += 256) s_Mp[i] = g_Mp[i];

    const float* xb = x + (size_t)(b * N_ + n) * D_;
    const float* mb = mx + ((size_t)(n * B_ + b) * T_) * D_;
    for (int i = tid; i < 8192; i += 256) {
        float mv = mb[i];
        float mv2 = __fadd_rn(__fmul_rn(0.05f, mv), __fmul_rn(0.95f, mv));
        s_p[i] = __fmul_rn(xb[(size_t)(i >> 7) * BND + (i & 127)], mv2);
    }
    __syncthreads();

    const int d = tid & 127;
    const int t2b = (tid >> 7) * 16;
    ull acc[16];
#pragma unroll
    for (int j = 0; j < 16; j++) acc[j] = 0ull;
    for (int s = 0; s < 64; s++) {
        ull cp = dup2(s_p[s * 128 + d]);
#pragma unroll
        for (int j = 0; j < 16; j++) ffma2(acc[j], s_Mp[(t2b + j) * 64 + s], cp);
    }
#pragma unroll
    for (int j = 0; j < 16; j++) {
        float2 f = *reinterpret_cast<float2*>(&acc[j]);
#pragma unroll
        for (int e = 0; e < 2; e++) {
            float v = (e == 0) ? f.x : f.y;
            size_t oi = ((size_t)(2 * (t2b + j) + e) * 4096 + bn) * 128 + d;
            __half hi = __float2half_rn(v);
            float r1 = __fsub_rn(v, __half2float(hi));
            g_ms[0][oi] = hi;
            g_ms[1][oi] = __float2half_rn(r1);
        }
    }
}

// =====================================================================
// GEMM tile (round-11 config). MODE 0: fp16 spikes. MODE 1: xg + splits.
// MODE 2: final fp32. MODE 3: ballot-packed spike masks (outp = uint32*).
// =====================================================================
constexpr int SGEMM = 1024 + 48 * 1024;   // 50176
constexpr int PPAD = 130;

template <int KCHUNKS, int MODE, int NSPLITS>
__device__ __forceinline__ void gemm_tile(
    int bn, const __half* __restrict__ aspl, size_t asstride,
    const __half* __restrict__ wsp,
    void* __restrict__ outp, int ldo, int ocol0,
    const float* __restrict__ gx,
    __half* __restrict__ so0, __half* __restrict__ so1,
    char* smem_raw) {
    const uint32_t sbase = smem_u32(smem_raw);
    float* s_pre = (float*)(smem_raw + 1024);
    const int tid = threadIdx.x;
    const int wid = tid >> 5, lane = tid & 31;
    constexpr int KTOT = KCHUNKS * 128;
    constexpr int NST = KCHUNKS * 2;

    const int n_base = wid * 32;
    const int sub = lane >> 3, lr = lane & 7;
    const int arow_off = (sub & 1) * 8 + lr;
    const int akc = (sub >> 1) * 8;
    const int brow_off = (sub >> 1) * 8 + lr;
    const int bkc = (sub & 1) * 8;

    float acc[4][4][4];
#pragma unroll
    for (int i = 0; i < 4; i++)
#pragma unroll
        for (int j = 0; j < 4; j++)
#pragma unroll
            for (int e = 0; e < 4; e++) acc[i][j][e] = 0.f;

#pragma unroll
    for (int s = 0; s < NST; s++) {
        if (s) __syncthreads();
        {
            const int ch = s >> 1, kh = s & 1;
            const uint32_t dst = sbase + 1024;
            for (int u = tid; u < NSPLITS * 512; u += 128) {
                int sp = u >> 9, r = u & 511, m = r >> 3, g = r & 7;
                const __half* src = aspl + (size_t)sp * asstride +
                    ((size_t)m * 4096 + bn) * KTOT + ch * 128 + kh * 64 + g * 8;
                cpa16(dst + sp * 8192 + sw128((m << 7) + (g << 4)), src);
            }
            for (int u = tid; u < 2048; u += 128) {
                int sp = u >> 10, r = u & 1023, n = r >> 3, g = r & 7;
                const __half* src =
                    wsp + ((size_t)(sp * 128 + n) * KTOT + ch * 128 + kh * 64 + g * 8);
                cpa16(dst + 16384 + sp * 16384 + sw128((n << 7) + (g << 4)), src);
            }
            cpa_commit();
        }
        cpa_wait<0>();
        __syncthreads();

        const uint32_t Abuf = sbase + 1024;
        const uint32_t Bbuf = Abuf + 16384;
        const int NP = (NSPLITS == 2) ? 3 : 2;
        const int PAs[3] = {0, 0, 1};
        const int PBs[3] = {0, 1, 0};
        const int PB1[3] = {0, 1, 0};

        for (int p = 0; p < NP; p++) {
            int As = (NSPLITS == 1) ? 0 : PAs[p];
            int Bs = (NSPLITS == 1) ? PB1[p] : PBs[p];
            uint32_t Abase = Abuf + As * 8192;
            uint32_t Bbase = Bbuf + Bs * 16384;
#pragma unroll
            for (int ks = 0; ks < 4; ks++) {
                int k0 = ks * 16;
                uint32_t afr[4][4];
#pragma unroll
                for (int mf = 0; mf < 4; mf++)
                    ldsm4(afr[mf], Abase +
                          sw128(((mf * 16 + arow_off) << 7) + (k0 + akc) * 2));
                uint32_t bfr[2][4];
#pragma unroll
                for (int nf2 = 0; nf2 < 2; nf2++)
                    ldsm4(bfr[nf2], Bbase +
                          sw128(((n_base + nf2 * 16 + brow_off) << 7) + (k0 + bkc) * 2));
#pragma unroll
                for (int mf = 0; mf < 4; mf++)
#pragma unroll
                    for (int nf = 0; nf < 4; nf++)
                        mma16816(acc[mf][nf], afr[mf],
                                 bfr[nf >> 1][(nf & 1) * 2], bfr[nf >> 1][(nf & 1) * 2 + 1]);
            }
        }
    }
    __syncthreads();

    {
        const int qr = lane >> 2, qc = (lane & 3) * 2;
#pragma unroll
        for (int mf = 0; mf < 4; mf++)
#pragma unroll
            for (int nf = 0; nf < 4; nf++) {
                int row = mf * 16 + qr;
                int col = n_base + nf * 8 + qc;
                *reinterpret_cast<float2*>(&s_pre[row * PPAD + col]) =
                    make_float2(acc[mf][nf][0], acc[mf][nf][1]);
                *reinterpret_cast<float2*>(&s_pre[(row + 8) * PPAD + col]) =
                    make_float2(acc[mf][nf][2], acc[mf][nf][3]);
            }
    }
    __syncthreads();

    {   // fused LIF scan: 128 threads = 128 columns
        const int c = tid;
        float vmem = 0.f;
        const size_t ostride = (size_t)4096 * ldo;
        const size_t obase = (size_t)bn * ldo + ocol0 + c;
        const size_t gbase = (size_t)bn * 128 + c;
        uint32_t* mout = (uint32_t*)outp;
#pragma unroll 1
        for (int t = 0; t < 64; t++) {
            float p = s_pre[t * PPAD + c];
            vmem = __fadd_rn(vmem, __fmul_rn(__fsub_rn(p, vmem), 0.5f));
            bool fire = (vmem >= 1.0f);
            float spk = fire ? 1.0f : 0.0f;
            if (fire) vmem = 0.0f;
            if (MODE == 3) {
                unsigned msk = __ballot_sync(0xffffffffu, fire);
                if (lane == 0) mout[((size_t)t * 4096 + bn) * 4 + wid] = msk;
            } else {
                size_t oi = obase + (size_t)t * ostride;
                if (MODE == 0) {
                    ((__half*)outp)[oi] = __float2half_rn(spk);
                } else {
                    float g = gx[gbase + (size_t)t * (size_t)BND];
                    float val = __fmul_rn(g, __fsub_rn(1.0f, spk));
                    ((float*)outp)[oi] = val;
                    if (MODE == 1) {
                        __half hi = __float2half_rn(val);
                        float r1 = __fsub_rn(val, __half2float(hi));
                        so0[oi] = hi;
                        so1[oi] = __float2half_rn(r1);
                    }
                }
            }
        }
    }
}

// =====================================================================
// Standalone GEMM kernels
// =====================================================================
template <int KCHUNKS, int MODEA, int MODEB, int NSPLITS, int NSEL>
__global__ void __launch_bounds__(128, 4) k_mmag(
    const __half* __restrict__ aspl, size_t asstride,
    const __half* __restrict__ wspA, const __half* __restrict__ wspB,
    void* __restrict__ outA, void* __restrict__ outB,
    int ldo, int ocolmul,
    const float* __restrict__ gx,
    __half* __restrict__ so0, __half* __restrict__ so1) {
    extern __shared__ __align__(16) char smem_raw[];
    const int sel = (NSEL == 2) ? (int)(blockIdx.x >> 12) : 0;
    const int bn = (NSEL == 2) ? (blockIdx.x & 4095) : blockIdx.x;
    if (sel)
        gemm_tile<KCHUNKS, MODEB, NSPLITS>(bn, aspl, asstride, wspB, outB,
            ldo, ocolmul, gx, so0, so1, smem_raw);
    else
        gemm_tile<KCHUNKS, MODEA, NSPLITS>(bn, aspl, asstride, wspA, outA,
            ldo, 0, gx, so0, so1, smem_raw);
}

// =====================================================================
// Attention: phase 1 POPC from spike masks (exact), phase 2 fp16 MMA.
// smem: s_v 2x8KB @0, s_at 2x8KB @16384, masks @32768 (2x1KB)
// =====================================================================
constexpr int SATT = 32768 + 2048;

__global__ void __launch_bounds__(256) k_attn4(const uint32_t* __restrict__ qm,
                                               const uint32_t* __restrict__ km,
                                               const __half* __restrict__ v,
                                               __half* __restrict__ so0,
                                               __half* __restrict__ so1) {
    extern __shared__ __align__(16) char sm_raw[];
    const uint32_t sbase = smem_u32(sm_raw);
    uint32_t* s_qw = (uint32_t*)(sm_raw + 32768);   // 256 words
    uint32_t* s_kw = s_qw + 256;
    const int tb = blockIdx.x;
    const int t = tb >> 6, b = tb & 63;
    const size_t base = (size_t)tb * 8192;
    const int tid = threadIdx.x;
    const int wid = tid >> 5, lane = tid & 31;

    // load v into transposed per-head tiles; load masks
    for (int u = tid; u < 4096; u += 256) {
        int n = u >> 6;
        int d = (u & 63) * 2;
        int h = d >> 6, dd = d & 63;
        uint32_t vp = *reinterpret_cast<const uint32_t*>(&v[base + 2 * u]);
        *reinterpret_cast<uint16_t*>(sm_raw + h * 8192 +
            sw128((dd << 7) + (n << 1))) = (uint16_t)(vp & 0xffffu);
        *reinterpret_cast<uint16_t*>(sm_raw + h * 8192 +
            sw128(((dd + 1) << 7) + (n << 1))) = (uint16_t)(vp >> 16);
    }
    if (tid < 256) {
        size_t mb = ((size_t)t * 4096 + b * 64) * 4;   // 256 words per (t,b)
        s_qw[tid] = qm[mb + tid];
        s_kw[tid] = km[mb + tid];
    }
    __syncthreads();

    // ---- phase 1: attn[h][n][m] = 0.125*popc(qm & km), fp16 into sw128 tile
    {
        const ull* q64 = (const ull*)s_qw;   // q64[n*2+h]
        const ull* k64 = (const ull*)s_kw;
        const int hn = tid >> 1;
        const int h = hn >> 6, n = hn & 63;
        const int mb0 = (tid & 1) * 32;
        ull qv = q64[n * 2 + h];
        char* atile = sm_raw + 16384 + h * 8192;
#pragma unroll
        for (int mm = 0; mm < 32; mm += 2) {
            int m = mb0 + mm;
            float a0 = 0.125f * (float)__popcll(qv & k64[m * 2 + h]);
            float a1 = 0.125f * (float)__popcll(qv & k64[(m + 1) * 2 + h]);
            *reinterpret_cast<uint32_t*>(atile + sw128((n << 7) + m * 2)) = h2x(a0, a1);
        }
    }
    __syncthreads();

    // ---- phase 2: o = attn . vT, emit exact 2-way fp16 splits ----
    {
        const int sub = lane >> 3, lr = lane & 7;
        const int arow_off = (sub & 1) * 8 + lr;
        const int akc = (sub >> 1) * 8;
        const int brow_off = (sub >> 1) * 8 + lr;
        const int bkc = (sub & 1) * 8;
        const int qr = lane >> 2, qc = (lane & 3) * 2;
        const int h = wid >> 2;
        const int n_b = (wid & 3) * 16;
        uint32_t Abase = sbase + 16384 + h * 8192;
        uint32_t Bbase = sbase + h * 8192;
        float acc[8][4];
#pragma unroll
        for (int j = 0; j < 8; j++)
#pragma unroll
            for (int e = 0; e < 4; e++) acc[j][e] = 0.f;
#pragma unroll
        for (int ks = 0; ks < 4; ks++) {
            int k0 = ks * 16;
            uint32_t afr[4];
            ldsm4(afr, Abase + sw128(((n_b + arow_off) << 7) + (k0 + akc) * 2));
#pragma unroll
            for (int df = 0; df < 4; df++) {
                uint32_t bfr[4];
                ldsm4(bfr, Bbase + sw128(((df * 16 + brow_off) << 7) + (k0 + bkc) * 2));
                mma16816(acc[df * 2 + 0], afr, bfr[0], bfr[1]);
                mma16816(acc[df * 2 + 1], afr, bfr[2], bfr[3]);
            }
        }
#pragma unroll
        for (int j = 0; j < 8; j++) {
            int d_col = h * 64 + j * 8 + qc;
#pragma unroll
            for (int half = 0; half < 2; half++) {
                int r0 = n_b + qr + half * 8;
                float f0 = acc[j][half * 2 + 0], f1 = acc[j][half * 2 + 1];
                float h0 = __half2float(__float2half_rn(f0));
                float h1v = __half2float(__float2half_rn(f1));
                size_t oi = base + (size_t)r0 * 128 + d_col;
                *reinterpret_cast<uint32_t*>(&so0[oi]) = h2x(f0, f1);
                *reinterpret_cast<uint32_t*>(&so1[oi]) =
                    h2x(__fsub_rn(f0, h0), __fsub_rn(f1, h1v));
            }
        }
    }
}

// =====================================================================
// Host side
// =====================================================================
extern "C" void kernel_launch(void* const* d_in, const int* in_sizes, int n_in,
                              void* d_out, int out_size) {
    const float* x  = (const float*)d_in[0];
    const float* mx = (const float*)d_in[1];
    const float* Wq = (const float*)d_in[2];
    const float* Wk = (const float*)d_in[3];
    const float* Wv = (const float*)d_in[4];
    const float* Wo = (const float*)d_in[5];
    const float* W1 = (const float*)d_in[6];
    const float* W2 = (const float*)d_in[7];
    float* out = (float*)d_out;

    void *p_xs, *p_ms, *p_os, *p_xgs, *p_xg, *p_qm, *p_km, *p_v, *p_h1, *p_wsp;
    cudaGetSymbolAddress(&p_xs, g_xs);
    cudaGetSymbolAddress(&p_ms, g_ms);
    cudaGetSymbolAddress(&p_os, g_os);
    cudaGetSymbolAddress(&p_xgs, g_xgs);
    cudaGetSymbolAddress(&p_xg, g_xg);
    cudaGetSymbolAddress(&p_qm, g_qm);
    cudaGetSymbolAddress(&p_km, g_km);
    cudaGetSymbolAddress(&p_v, g_v);
    cudaGetSymbolAddress(&p_h1, g_h1);
    cudaGetSymbolAddress(&p_wsp, g_wsp);
    __half* xs = (__half*)p_xs;
    __half* ms = (__half*)p_ms;
    __half* os = (__half*)p_os;
    __half* xgs = (__half*)p_xgs;
    __half* wsp = (__half*)p_wsp;
    const size_t WSTRIDE = 2 * 128 * 256;

    cudaFuncSetAttribute(k_mmag<1, 3, 3, 2, 1>, cudaFuncAttributeMaxDynamicSharedMemorySize, SGEMM);
    cudaFuncSetAttribute(k_mmag<1, 3, 0, 2, 2>, cudaFuncAttributeMaxDynamicSharedMemorySize, SGEMM);
    cudaFuncSetAttribute(k_mmag<1, 1, 1, 2, 1>, cudaFuncAttributeMaxDynamicSharedMemorySize, SGEMM);
    cudaFuncSetAttribute(k_mmag<1, 0, 0, 2, 2>, cudaFuncAttributeMaxDynamicSharedMemorySize, SGEMM);
    cudaFuncSetAttribute(k_mmag<2, 2, 2, 1, 1>, cudaFuncAttributeMaxDynamicSharedMemorySize, SGEMM);
    cudaFuncSetAttribute(k_attn4, cudaFuncAttributeMaxDynamicSharedMemorySize, SATT);

    // 1: prep (xsplit + wsplit + dct-pack)
    k_prep<<<2568, 256>>>(x, Wq, Wk, Wv, Wo, W1, W2);
    // 2: mix -> mlp splits
    k_mix<<<4096, 256>>>(x, mx);
    // 3: q masks = LIF(x @ Wq)
    k_mmag<1, 3, 3, 2, 1><<<4096, 128, SGEMM>>>(xs, TOT, wsp + 0 * WSTRIDE, nullptr,
        p_qm, nullptr, 128, 0, nullptr, nullptr, nullptr);
    // 4: k masks / v spikes = LIF(mlp @ Wk/Wv)  <- profiled
    k_mmag<1, 3, 0, 2, 2><<<8192, 128, SGEMM>>>(ms, TOT, wsp + 1 * WSTRIDE,
        wsp + 2 * WSTRIDE, p_qm == nullptr ? nullptr : p_km, p_v, 128, 0,
        nullptr, nullptr, nullptr);
    // 5: attention (POPC phase 1)
    k_attn4<<<4096, 256, SATT>>>((const uint32_t*)p_qm, (const uint32_t*)p_km,
        (const __half*)p_v, os, os + TOT);
    // 6: xg = x * (1 - LIF(o @ Wo))
    k_mmag<1, 1, 1, 2, 1><<<4096, 128, SGEMM>>>(os, TOT, wsp + 3 * WSTRIDE, nullptr,
        p_xg, nullptr, 128, 0, x, xgs, xgs + TOT);
    // 7: h1 = LIF(xg @ W1) (both N-halves fused)
    k_mmag<1, 0, 0, 2, 2><<<8192, 128, SGEMM>>>(xgs, TOT, wsp + 4 * WSTRIDE,
        wsp + 5 * WSTRIDE, p_h1, p_h1, 256, 128, nullptr, nullptr, nullptr);
    // 8: out = xg * (1 - LIF(h1 @ W2))
    k_mmag<2, 2, 2, 1, 1><<<4096, 128, SGEMM>>>((const __half*)p_h1, 0,
        wsp + 6 * WSTRIDE, nullptr, out, nullptr, 128, 0, (const float*)p_xg,
        nullptr, nullptr);
}